// round 4
// baseline (speedup 1.0000x reference)
#include <cuda_runtime.h>
#include <cstdint>

#define N_   16
#define T_   32
#define D_   768
#define L_   196
#define DC   8
#define NCH  (D_ / DC)   // 96 chunks
#define NLB  7
#define NBUF 3

typedef unsigned long long u64;

// dynamic smem: float sk[NBUF][DC][32][32]  (96 KB)
extern __shared__ float smem_[];
#define SK(b, dd, s, l) smem_[((((b) * DC + (dd)) * 32 + (s)) * 32) + (l)]
#define SK_BYTES (NBUF * DC * 32 * 32 * 4)

// ---- packed f32x2 helpers ----
__device__ __forceinline__ u64 pack2(float x, float y) {
    u64 r; asm("mov.b64 %0, {%1, %2};" : "=l"(r) : "f"(x), "f"(y)); return r;
}
__device__ __forceinline__ void unpack2(u64 v, float& x, float& y) {
    asm("mov.b64 {%0, %1}, %2;" : "=f"(x), "=f"(y) : "l"(v));
}
__device__ __forceinline__ u64 fma2_(u64 a, u64 b, u64 c) {
    u64 r; asm("fma.rn.f32x2 %0, %1, %2, %3;" : "=l"(r) : "l"(a), "l"(b), "l"(c)); return r;
}

// ---- cp.async ----
__device__ __forceinline__ void cp16(void* dst, const float* src) {
    uint32_t d = (uint32_t)__cvta_generic_to_shared(dst);
    asm volatile("cp.async.ca.shared.global [%0], [%1], 16;" :: "r"(d), "l"(src));
}
__device__ __forceinline__ void cp_commit() { asm volatile("cp.async.commit_group;"); }
__device__ __forceinline__ void cp_wait1()  { asm volatile("cp.async.wait_group 1;"); }
__device__ __forceinline__ void cp_wait0()  { asm volatile("cp.async.wait_group 0;"); }

// =====================================================================
// Fused temporal cross-attention.
// Grid (7, 16, 2) — (l-block, n, t-half). Block 128 = 32 l-lanes x 4
// warps, each warp owns 4 t's. Phase 1 streams k (triple-buffered
// cp.async, 1 barrier/chunk), accumulating S'= (q+eq)·k as f32x2 pairs
// over s. Softmax is thread-local; weights stay in registers. Phase 2
// streams k again for out = A·k + ek, stores float4-coalesced along d.
// =====================================================================
__global__ __launch_bounds__(128, 2)
void tca_fused_kernel(const float* __restrict__ q, const float* __restrict__ k,
                      const float* __restrict__ peq, const float* __restrict__ pek,
                      float* __restrict__ out)
{
    const int tid  = threadIdx.x;
    const int lane = tid & 31;
    const int tg   = tid >> 5;                 // 0..3
    const int l0   = blockIdx.x * 32;
    const int n    = blockIdx.y;
    const int t0   = blockIdx.z * 16 + tg * 4;
    const int l    = l0 + lane;
    const bool lv  = (l < L_);

    // staging map: fixed l-quad per thread
    const int ll  = (tid & 7) * 4;
    const bool sv = (l0 + ll < L_);
    const int rr  = tid >> 3;                  // 0..15

    // zero smem once (invalid l slots stay zero forever)
    for (int i = tid; i < NBUF * DC * 32 * 32; i += 128) smem_[i] = 0.f;
    __syncthreads();

    const float* kbase = k + (size_t)n * T_ * D_ * L_ + l0 + ll;

    auto issue = [&](int c, int buf) {
        const int d0 = c * DC;
        if (sv) {
#pragma unroll
            for (int i = 0; i < 16; i++) {
                int r  = i * 16 + rr;          // 0..255
                int s  = r & 31;
                int dd = r >> 5;
                cp16(&SK(buf, dd, s, ll), kbase + ((size_t)s * D_ + d0 + dd) * L_);
            }
        }
        cp_commit();
    };

    // q chunk with peq folded in: qp = q + eq (the (q+eq)·ek term is
    // constant over s and cancels in the softmax)
    auto loadq = [&](int c, float (&qr)[4][DC]) {
        const int d0 = c * DC;
        if (lv) {
            float e[8];
            float4 e0 = *reinterpret_cast<const float4*>(peq + l * D_ + d0);
            float4 e1 = *reinterpret_cast<const float4*>(peq + l * D_ + d0 + 4);
            e[0] = e0.x; e[1] = e0.y; e[2] = e0.z; e[3] = e0.w;
            e[4] = e1.x; e[5] = e1.y; e[6] = e1.z; e[7] = e1.w;
#pragma unroll
            for (int i = 0; i < 4; i++)
#pragma unroll
                for (int dd = 0; dd < DC; dd++)
                    qr[i][dd] = __ldg(q + (((size_t)n * T_ + t0 + i) * D_ + d0 + dd) * L_ + l)
                                + e[dd];
        } else {
#pragma unroll
            for (int i = 0; i < 4; i++)
#pragma unroll
                for (int dd = 0; dd < DC; dd++) qr[i][dd] = 0.f;
        }
    };

    auto loadpe = [&](int c, float (&pe)[8]) {
        if (lv) {
            const int d0 = c * DC;
            float4 a = *reinterpret_cast<const float4*>(pek + l * D_ + d0);
            float4 b = *reinterpret_cast<const float4*>(pek + l * D_ + d0 + 4);
            pe[0] = a.x; pe[1] = a.y; pe[2] = a.z; pe[3] = a.w;
            pe[4] = b.x; pe[5] = b.y; pe[6] = b.z; pe[7] = b.w;
        } else {
#pragma unroll
            for (int i = 0; i < 8; i++) pe[i] = 0.f;
        }
    };

    // ---------------- Phase 1: scores ----------------
    u64 acc[4][16];
#pragma unroll
    for (int i = 0; i < 4; i++)
#pragma unroll
        for (int sp = 0; sp < 16; sp++) acc[i][sp] = 0ULL;

    float qc[4][DC], qn[4][DC];
    issue(0, 0);
    issue(1, 1);
    loadq(0, qc);

    for (int c = 0; c < NCH; ++c) {
        if (c + 1 < NCH) cp_wait1(); else cp_wait0();
        __syncthreads();
        if (c + 2 < NCH) issue(c + 2, (c + 2) % NBUF);
        if (c + 1 < NCH) loadq(c + 1, qn);

        const int buf = c % NBUF;
#pragma unroll
        for (int dd = 0; dd < DC; dd++) {
            u64 qv0 = pack2(qc[0][dd], qc[0][dd]);
            u64 qv1 = pack2(qc[1][dd], qc[1][dd]);
            u64 qv2 = pack2(qc[2][dd], qc[2][dd]);
            u64 qv3 = pack2(qc[3][dd], qc[3][dd]);
            const float* kb = &SK(buf, dd, 0, lane);
#pragma unroll
            for (int sp = 0; sp < 16; sp++) {
                u64 kv = pack2(kb[(2 * sp) * 32], kb[(2 * sp + 1) * 32]);
                acc[0][sp] = fma2_(qv0, kv, acc[0][sp]);
                acc[1][sp] = fma2_(qv1, kv, acc[1][sp]);
                acc[2][sp] = fma2_(qv2, kv, acc[2][sp]);
                acc[3][sp] = fma2_(qv3, kv, acc[3][sp]);
            }
        }
#pragma unroll
        for (int i = 0; i < 4; i++)
#pragma unroll
            for (int dd = 0; dd < DC; dd++) qc[i][dd] = qn[i][dd];
    }

    // prime phase-2 pipeline before softmax so staging overlaps it
    // (bufs 0 and 1 were last consumed at chunks 93/94 — all threads
    // passed the c=95 barrier, so overwrite is safe)
    issue(0, 0);
    issue(1, 1);

    // ---------------- softmax (thread-local, weights -> registers) ----
    float ar[4][32];
    {
        const float scale = 0.03608439182435161f;  // 1/sqrt(768)
#pragma unroll
        for (int i = 0; i < 4; i++) {
            float v[32];
#pragma unroll
            for (int sp = 0; sp < 16; sp++) unpack2(acc[i][sp], v[2 * sp], v[2 * sp + 1]);
            float m = -1e30f;
#pragma unroll
            for (int s = 0; s < 32; s++) { v[s] *= scale; m = fmaxf(m, v[s]); }
            float sum = 0.f;
#pragma unroll
            for (int s = 0; s < 32; s++) { float e = __expf(v[s] - m); v[s] = e; sum += e; }
            float inv = 1.f / sum;
#pragma unroll
            for (int s = 0; s < 32; s++) ar[i][s] = v[s] * inv;
        }
    }

    // ---------------- Phase 2: out = A·k + ek ----------------
    float pec[8], pen[8];
    loadpe(0, pec);

    for (int c = 0; c < NCH; ++c) {
        if (c + 1 < NCH) cp_wait1(); else cp_wait0();
        __syncthreads();
        if (c + 2 < NCH) issue(c + 2, (c + 2) % NBUF);
        if (c + 1 < NCH) loadpe(c + 1, pen);

        const int buf = c % NBUF;
        u64 oc[4][4];
#pragma unroll
        for (int i = 0; i < 4; i++)
#pragma unroll
            for (int dp = 0; dp < 4; dp++) oc[i][dp] = 0ULL;

#pragma unroll
        for (int s = 0; s < 32; s++) {
            const float* kb = &SK(buf, 0, s, lane);
            u64 kv0 = pack2(kb[0 * 1024], kb[1 * 1024]);
            u64 kv1 = pack2(kb[2 * 1024], kb[3 * 1024]);
            u64 kv2 = pack2(kb[4 * 1024], kb[5 * 1024]);
            u64 kv3 = pack2(kb[6 * 1024], kb[7 * 1024]);
#pragma unroll
            for (int i = 0; i < 4; i++) {
                u64 a2 = pack2(ar[i][s], ar[i][s]);
                oc[i][0] = fma2_(a2, kv0, oc[i][0]);
                oc[i][1] = fma2_(a2, kv1, oc[i][1]);
                oc[i][2] = fma2_(a2, kv2, oc[i][2]);
                oc[i][3] = fma2_(a2, kv3, oc[i][3]);
            }
        }

        if (lv) {
            const int d0 = c * DC;
#pragma unroll
            for (int i = 0; i < 4; i++) {
                float* op = out + (((size_t)n * T_ + t0 + i) * L_ + l) * D_ + d0;
                float4 fa, fb;
                unpack2(oc[i][0], fa.x, fa.y);
                unpack2(oc[i][1], fa.z, fa.w);
                unpack2(oc[i][2], fb.x, fb.y);
                unpack2(oc[i][3], fb.z, fb.w);
                fa.x += pec[0]; fa.y += pec[1]; fa.z += pec[2]; fa.w += pec[3];
                fb.x += pec[4]; fb.y += pec[5]; fb.z += pec[6]; fb.w += pec[7];
                *reinterpret_cast<float4*>(op)     = fa;
                *reinterpret_cast<float4*>(op + 4) = fb;
            }
        }
#pragma unroll
        for (int i = 0; i < 8; i++) pec[i] = pen[i];
    }
}

extern "C" void kernel_launch(void* const* d_in, const int* in_sizes, int n_in,
                              void* d_out, int out_size)
{
    const float* q   = (const float*)d_in[0];
    const float* k   = (const float*)d_in[1];
    const float* peq = (const float*)d_in[2];
    const float* pek = (const float*)d_in[3];
    float* out = (float*)d_out;

    static int configured = 0;
    if (!configured) {
        cudaFuncSetAttribute(tca_fused_kernel,
                             cudaFuncAttributeMaxDynamicSharedMemorySize, SK_BYTES);
        configured = 1;
    }

    dim3 grid(NLB, N_, 2);
    tca_fused_kernel<<<grid, 128, SK_BYTES>>>(q, k, peq, pek, out);
}